// round 8
// baseline (speedup 1.0000x reference)
#include <cuda_runtime.h>
#include <cuda_bf16.h>
#include <cstdint>

#define BB 8
#define NN 2048
#define DD 128
#define NEG 0.2f
#define BN (BB*NN)

#define KCHUNK 64
#define NCHUNKS (NN/KCHUNK)   // 32
#define TILE_N 64

// ---------------- scratch (device globals) ----------------
__device__ __align__(16) unsigned short g_hT1[(size_t)BB*DD*NN];  // bf16 hi part of h^T [b][d][m]
__device__ __align__(16) unsigned short g_hT2[(size_t)BB*DD*NN];  // bf16 residual part
__device__ __align__(16) float  g_eA[BN];              // exp(s_i)
__device__ __align__(16) float  g_eC[BN];              // exp(0.2 s_i)
__device__ __align__(16) float2 g_e12[BN];             // {exp(s_j), exp(0.2 s_j)}
__device__ __align__(16) unsigned g_adj[NN*(NN/32)];   // packed adjacency bitmask

// ---------------- helpers ----------------
__device__ __forceinline__ uint32_t smem_to_u32(const void* p) {
    uint32_t a;
    asm("{ .reg .u64 t; cvta.to.shared.u64 t, %1; cvt.u32.u64 %0, t; }"
        : "=r"(a) : "l"(p));
    return a;
}
#define SW128(off) ((off) ^ (((off) >> 3) & 0x70))

__device__ __forceinline__ void ldsm4(uint32_t* r, uint32_t addr) {
    asm volatile("ldmatrix.sync.aligned.m8n8.x4.shared.b16 {%0,%1,%2,%3}, [%4];"
        : "=r"(r[0]), "=r"(r[1]), "=r"(r[2]), "=r"(r[3]) : "r"(addr));
}
__device__ __forceinline__ void mma_bf16(float* c, const uint32_t* a,
                                         uint32_t b0, uint32_t b1) {
    asm volatile(
        "mma.sync.aligned.m16n8k16.row.col.f32.bf16.bf16.f32 "
        "{%0,%1,%2,%3}, {%4,%5,%6,%7}, {%8,%9}, {%0,%1,%2,%3};"
        : "+f"(c[0]), "+f"(c[1]), "+f"(c[2]), "+f"(c[3])
        : "r"(a[0]), "r"(a[1]), "r"(a[2]), "r"(a[3]), "r"(b0), "r"(b1));
}

#define CP_ASYNC16(dst, src) \
    asm volatile("cp.async.cg.shared.global [%0], [%1], 16;" \
        :: "r"(dst), "l"(src) : "memory")
#define CP_COMMIT() asm volatile("cp.async.commit_group;" ::: "memory")
#define CP_WAIT1()  asm volatile("cp.async.wait_group 1;" ::: "memory")

// bf16 2-term split: p1 = bf16x2(a0,a1) (lo=a0), p2 = bf16x2 of residuals
__device__ __forceinline__ void bsplit(float a0, float a1, unsigned& p1, unsigned& p2) {
    asm("cvt.rn.bf16x2.f32 %0, %2, %1;" : "=r"(p1) : "f"(a0), "f"(a1));
    float b0 = __uint_as_float(p1 << 16);
    float b1 = __uint_as_float(p1 & 0xffff0000u);
    float r0 = a0 - b0, r1 = a1 - b1;
    asm("cvt.rn.bf16x2.f32 %0, %2, %1;" : "=r"(p2) : "f"(r0), "f"(r1));
}

// ---------------- fused: h = x@W (+splits, s/exp) AND adj packing ----------------
// blocks [0,256): h-work, 64 rows each; blocks [256, 2304): pack one adj row
__global__ void __launch_bounds__(256) k_pre(const float* __restrict__ x,
                                             const float* __restrict__ W,
                                             const float* __restrict__ a_vec,
                                             const int* __restrict__ adj) {
    __shared__ float xs[64*128];
    int tid = threadIdx.x;

    if (blockIdx.x >= 256) {
        // ---- pack: one row, int4 loads, byte-assembled ballot ----
        int row = blockIdx.x - 256;
        int lane = tid & 31;
        const int4* src = (const int4*)(adj + (size_t)row*NN);
        int4 p = src[tid*2], q = src[tid*2+1];
        unsigned bb = ((p.x>0)?1u:0u) | ((p.y>0)?2u:0u) | ((p.z>0)?4u:0u) | ((p.w>0)?8u:0u)
                    | ((q.x>0)?16u:0u) | ((q.y>0)?32u:0u) | ((q.z>0)?64u:0u) | ((q.w>0)?128u:0u);
        unsigned v = bb << (8*(lane & 3));
        v |= __shfl_xor_sync(0xffffffffu, v, 1);
        v |= __shfl_xor_sync(0xffffffffu, v, 2);
        if ((lane & 3) == 0) g_adj[row*64 + (tid >> 2)] = v;
        return;
    }

    // ---- h-work: 64 rows per block, two 128-thread halves of 32 rows ----
    int hid = tid >> 7, t = tid & 127;
    int row0 = blockIdx.x * 64;
    for (int i = tid; i < 64*128; i += 256) xs[i] = x[(size_t)row0*128 + i];
    __syncthreads();

    float acc[32];
#pragma unroll
    for (int r = 0; r < 32; r++) acc[r] = 0.f;
    const float* xsl = xs + hid*32*128;
#pragma unroll 2
    for (int k = 0; k < 128; k++) {
        float wv = W[k*128 + t];
#pragma unroll
        for (int r = 0; r < 32; r++) acc[r] += xsl[r*128 + k] * wv;
    }
    // write hT bf16 split: thread = d column, rows = 32 consecutive m
    int grow0 = row0 + hid*32;
    int b = grow0 >> 11, mbase = grow0 & 2047;
    {
        unsigned u1[16], u2[16];
#pragma unroll
        for (int k = 0; k < 16; k++) bsplit(acc[2*k], acc[2*k+1], u1[k], u2[k]);
        size_t base = ((size_t)(b*DD + t) * NN + mbase) >> 1;
        uint4* d1 = (uint4*)((unsigned*)g_hT1 + base);
        uint4* d2 = (uint4*)((unsigned*)g_hT2 + base);
#pragma unroll
        for (int k = 0; k < 4; k++) {
            d1[k] = *(uint4*)(u1 + 4*k);
            d2[k] = *(uint4*)(u2 + 4*k);
        }
    }
    // s reduction (reuse xs)
    __syncthreads();
#pragma unroll
    for (int r = 0; r < 32; r++) xs[(hid*32 + r)*128 + t] = acc[r];
    __syncthreads();
    int wid = tid >> 5, lane = tid & 31;
    float4 a14 = *(const float4*)(a_vec + lane*4);
    float4 a24 = *(const float4*)(a_vec + 128 + lane*4);
#pragma unroll
    for (int k = 0; k < 8; k++) {
        int r = wid*8 + k;
        float4 hv = *(const float4*)(xs + r*128 + lane*4);
        float s1 = hv.x*a14.x + hv.y*a14.y + hv.z*a14.z + hv.w*a14.w;
        float s2 = hv.x*a24.x + hv.y*a24.y + hv.z*a24.z + hv.w*a24.w;
#pragma unroll
        for (int o = 16; o; o >>= 1) {
            s1 += __shfl_xor_sync(0xffffffffu, s1, o);
            s2 += __shfl_xor_sync(0xffffffffu, s2, o);
        }
        if (lane == 0) {
            int gr = row0 + r;
            g_eA[gr] = __expf(s1);
            g_eC[gr] = __expf(NEG * s1);
            g_e12[gr] = make_float2(__expf(s2), __expf(NEG * s2));
        }
    }
}

// ---------------- smem layout (97 KB → 2 CTAs/SM) ----------------
#define SM_A1   0u          // 8 KB (64 x 128B)
#define SM_A2   8192u       // 8 KB
#define SM_B    16384u      // 64 KB: 2 bufs x (B1 16KB + B2 16KB)
#define SM_ADJ  81920u      // 16 KB (64 rows x 64 words)
#define SM_ROW  98304u      // 3 x 64 floats
#define SM_TOTAL (98304 + 768)

// ---------------- fused softmax + alpha + HMMA alpha@h ----------------
// grid (32, 8), block 256 (8 warps), 2 CTAs/SM
__global__ void __launch_bounds__(256, 2) k_main(float* __restrict__ out,
                                                 float* __restrict__ alpha) {
    extern __shared__ __align__(1024) char smem[];
    uint32_t sb = smem_to_u32(smem);
    int tid = threadIdx.x, wid = tid >> 5, lane = tid & 31;
    int b = blockIdx.y, n0 = blockIdx.x * TILE_N;

    unsigned* adjs = (unsigned*)(smem + SM_ADJ);
    float* AiSh = (float*)(smem + SM_ROW);
    float* CiSh = AiSh + TILE_N;
    float* RvSh = CiSh + TILE_N;
    const float* e12g = (const float*)(g_e12 + b*NN);

    // stage adj bitmask (16KB)
    {
        const uint4* s = (const uint4*)(g_adj + (size_t)n0*64);
        uint4* d = (uint4*)adjs;
#pragma unroll
        for (int k = 0; k < 4; k++) d[tid + k*256] = s[tid + k*256];
    }
    if (tid < TILE_N) {
        AiSh[tid] = g_eA[b*NN + n0 + tid];
        CiSh[tid] = g_eC[b*NN + n0 + tid];
    }

    // B cp.async staging setup: split = tid&1, row = tid>>1, 8 x 16B each
    int bsplit_sel = tid & 1, brow2 = tid >> 1;
    const unsigned short* gsrc = bsplit_sel ? g_hT2 : g_hT1;
    const char* gsrc_row = (const char*)(gsrc + ((size_t)(b*128 + brow2)) * NN);
    unsigned b_xor_st = (unsigned)((brow2 & 7) << 4);
    uint32_t bst_base = sb + SM_B + bsplit_sel*16384u + (unsigned)(brow2*128);

    // prologue: issue B copies for chunk 0
    {
        const char* src = gsrc_row;   // m0 = 0
#pragma unroll
        for (int i = 0; i < 8; i++)
            CP_ASYNC16(bst_base + ((i*16u) ^ b_xor_st), src + i*16);
        CP_COMMIT();
    }
    __syncthreads();

    // ---- pass B: row softmax denominators (8 rows per warp) ----
#pragma unroll 1
    for (int k = 0; k < 8; k++) {
        int r = wid*8 + k;
        float Ai = AiSh[r], Ci = CiSh[r];
        const unsigned* arow = adjs + r*64;
        float sum = 0.f;
#pragma unroll 4
        for (int i2 = 0; i2 < 32; i2++) {
            float4 ev = __ldg((const float4*)(e12g + (i2*128 + lane*4)));
            unsigned bits = arow[i2*2 + (lane >> 4)];
            unsigned bp = (lane & 15) * 2;
            float nu0 = fmaxf(Ai*ev.x, Ci*ev.y);
            float nu1 = fmaxf(Ai*ev.z, Ci*ev.w);
            sum += ((bits >> bp) & 1u) ? nu0 : 0.f;
            sum += ((bits >> (bp+1)) & 1u) ? nu1 : 0.f;
        }
#pragma unroll
        for (int o = 16; o; o >>= 1) sum += __shfl_xor_sync(0xffffffffu, sum, o);
        if (lane == 0) RvSh[r] = 1.f / sum;
    }
    __syncthreads();

    // alpha mapping: row = tid>>2, 16-m quarter = tid&3
    int arw = tid >> 2, mq = tid & 3;
    float Ai = AiSh[arw], Ci = CiSh[arw], Rv = RvSh[arw];
    float* aout = alpha + ((size_t)(b*NN + n0 + arw)) * NN;

    // warp GEMM tiling: warp -> n-half 32, d-quarter 32
    int n0w = (wid >> 2) * 32, d0w = (wid & 3) * 32;
    int arow_l = lane & 15;
    unsigned acol_l = (lane >> 4) * 16;
    int brow_l = (lane & 7) + ((lane >> 4) << 3);
    unsigned bcol_l = ((lane >> 3) & 1) * 16;
    unsigned a_xor = (unsigned)((arow_l & 7) << 4);
    unsigned b_xor = (unsigned)((brow_l & 7) << 4);
    uint32_t a_row_base = sb + SM_A1 + (unsigned)((n0w + arow_l) * 128);
    uint32_t b_row_off  = (unsigned)((d0w + brow_l) * 128);

    float acc[2][4][4];
#pragma unroll
    for (int i = 0; i < 2; i++)
#pragma unroll
        for (int j = 0; j < 4; j++)
#pragma unroll
            for (int k = 0; k < 4; k++) acc[i][j][k] = 0.f;

    for (int c = 0; c < NCHUNKS; c++) {
        int m0 = c * KCHUNK;
        // issue cp.async for next chunk into the other buffer
        if (c + 1 < NCHUNKS) {
            const char* src = gsrc_row + (size_t)(m0 + KCHUNK)*2;
            uint32_t dst = bst_base + ((unsigned)((c+1) & 1))*32768u;
#pragma unroll
            for (int i = 0; i < 8; i++)
                CP_ASYNC16(dst + ((i*16u) ^ b_xor_st), src + i*16);
        }
        CP_COMMIT();
        CP_WAIT1();   // chunk c's B copies complete

        // alpha: 16 m per thread (exact fp32 STG + bf16 split STS into A tiles)
        unsigned bits = adjs[arw*64 + c*2 + (mq >> 1)];
        unsigned shbase = (mq & 1) * 16;
#pragma unroll
        for (int g = 0; g < 4; g++) {
            int mloc = mq*16 + g*4;
            int m = m0 + mloc;
            float4 e01 = __ldg((const float4*)(e12g + 2*m));
            float4 e23 = __ldg((const float4*)(e12g + 2*m + 4));
            float n0v = fmaxf(Ai*e01.x, Ci*e01.y);
            float n1v = fmaxf(Ai*e01.z, Ci*e01.w);
            float n2v = fmaxf(Ai*e23.x, Ci*e23.y);
            float n3v = fmaxf(Ai*e23.z, Ci*e23.w);
            unsigned bp = shbase + g*4;
            float a0 = ((bits >> (bp+0)) & 1u) ? n0v*Rv : 0.f;
            float a1 = ((bits >> (bp+1)) & 1u) ? n1v*Rv : 0.f;
            float a2 = ((bits >> (bp+2)) & 1u) ? n2v*Rv : 0.f;
            float a3 = ((bits >> (bp+3)) & 1u) ? n3v*Rv : 0.f;
            *(float4*)(aout + m) = make_float4(a0, a1, a2, a3);
            unsigned p1a, p2a, p1b, p2b;
            bsplit(a0, a1, p1a, p2a);
            bsplit(a2, a3, p1b, p2b);
            unsigned so = SW128((unsigned)(arw*128 + mloc*2));
            *(uint2*)(smem + SM_A1 + so) = make_uint2(p1a, p1b);
            *(uint2*)(smem + SM_A2 + so) = make_uint2(p2a, p2b);
        }
        __syncthreads();

        uint32_t b_base = sb + SM_B + ((unsigned)(c & 1))*32768u + b_row_off;
        // MMA: 4 k-steps of 16, term-major ordering (no acc RAW chains)
#pragma unroll
        for (int ks = 0; ks < 4; ks++) {
            unsigned acol = (acol_l + ks*32) ^ a_xor;
            unsigned bcol = (bcol_l + ks*32) ^ b_xor;
            uint32_t a1f[2][4], a2f[2][4], b1f[2][4], b2f[2][4];
#pragma unroll
            for (int ng = 0; ng < 2; ng++) {
                ldsm4(a1f[ng], a_row_base + ng*2048 + acol);
                ldsm4(a2f[ng], a_row_base + ng*2048 + acol + 8192u);
            }
#pragma unroll
            for (int dg = 0; dg < 2; dg++) {
                ldsm4(b1f[dg], b_base + dg*2048 + bcol);
                ldsm4(b2f[dg], b_base + dg*2048 + bcol + 16384u);
            }
            // term 1: a1*h1
#pragma unroll
            for (int ng = 0; ng < 2; ng++)
#pragma unroll
                for (int dg = 0; dg < 2; dg++) {
                    mma_bf16(acc[ng][dg*2+0], a1f[ng], b1f[dg][0], b1f[dg][1]);
                    mma_bf16(acc[ng][dg*2+1], a1f[ng], b1f[dg][2], b1f[dg][3]);
                }
            // term 2: a1*h2
#pragma unroll
            for (int ng = 0; ng < 2; ng++)
#pragma unroll
                for (int dg = 0; dg < 2; dg++) {
                    mma_bf16(acc[ng][dg*2+0], a1f[ng], b2f[dg][0], b2f[dg][1]);
                    mma_bf16(acc[ng][dg*2+1], a1f[ng], b2f[dg][2], b2f[dg][3]);
                }
            // term 3: a2*h1
#pragma unroll
            for (int ng = 0; ng < 2; ng++)
#pragma unroll
                for (int dg = 0; dg < 2; dg++) {
                    mma_bf16(acc[ng][dg*2+0], a2f[ng], b1f[dg][0], b1f[dg][1]);
                    mma_bf16(acc[ng][dg*2+1], a2f[ng], b1f[dg][2], b1f[dg][3]);
                }
        }
        __syncthreads();
    }

    // epilogue: write out tile
#pragma unroll
    for (int ng = 0; ng < 2; ng++) {
#pragma unroll
        for (int dt = 0; dt < 4; dt++) {
            int r = n0 + n0w + ng*16 + (lane >> 2);
            int col = d0w + dt*8 + (lane & 3)*2;
            float* p = out + ((size_t)(b*NN + r))*DD + col;
            *(float2*)p = make_float2(acc[ng][dt][0], acc[ng][dt][1]);
            *(float2*)(p + 8*DD) = make_float2(acc[ng][dt][2], acc[ng][dt][3]);
        }
    }
}

// ---------------- launch ----------------
extern "C" void kernel_launch(void* const* d_in, const int* in_sizes, int n_in,
                              void* d_out, int out_size) {
    const float* x    = (const float*)d_in[0];
    const int*   adj  = (const int*)  d_in[1];
    const float* W    = (const float*)d_in[2];
    const float* avec = (const float*)d_in[3];
    float* out   = (float*)d_out;
    float* alpha = out + (size_t)BN*DD;

    cudaFuncSetAttribute(k_main, cudaFuncAttributeMaxDynamicSharedMemorySize,
                         SM_TOTAL);

    k_pre<<<256 + NN, 256>>>(x, W, avec, adj);
    dim3 grid(NN/TILE_N, BB);
    k_main<<<grid, 256, SM_TOTAL>>>(out, alpha);
}

// round 9
// speedup vs baseline: 1.1905x; 1.1905x over previous
#include <cuda_runtime.h>
#include <cuda_bf16.h>
#include <cstdint>

#define BB 8
#define NN 2048
#define DD 128
#define NEG 0.2f
#define BN (BB*NN)

#define KCHUNK 64
#define NCHUNKS (NN/KCHUNK)   // 32
#define TILE_N 64

// ---------------- scratch (device globals) ----------------
__device__ __align__(16) unsigned short g_hT1[(size_t)BB*DD*NN];  // bf16 hi part of h^T [b][d][m]
__device__ __align__(16) unsigned short g_hT2[(size_t)BB*DD*NN];  // bf16 residual part
__device__ __align__(16) float  g_eA[BN];              // exp(s_i)
__device__ __align__(16) float  g_eC[BN];              // exp(0.2 s_i)
__device__ __align__(16) float2 g_e12[BN];             // {exp(s_j), exp(0.2 s_j)}
__device__ __align__(16) unsigned g_adj[NN*(NN/32)];   // packed adjacency bitmask

// ---------------- helpers ----------------
__device__ __forceinline__ uint32_t smem_to_u32(const void* p) {
    uint32_t a;
    asm("{ .reg .u64 t; cvta.to.shared.u64 t, %1; cvt.u32.u64 %0, t; }"
        : "=r"(a) : "l"(p));
    return a;
}
#define SW128(off) ((off) ^ (((off) >> 3) & 0x70))

__device__ __forceinline__ void ldsm4(uint32_t* r, uint32_t addr) {
    asm volatile("ldmatrix.sync.aligned.m8n8.x4.shared.b16 {%0,%1,%2,%3}, [%4];"
        : "=r"(r[0]), "=r"(r[1]), "=r"(r[2]), "=r"(r[3]) : "r"(addr));
}
__device__ __forceinline__ void mma_bf16(float* c, const uint32_t* a,
                                         uint32_t b0, uint32_t b1) {
    asm volatile(
        "mma.sync.aligned.m16n8k16.row.col.f32.bf16.bf16.f32 "
        "{%0,%1,%2,%3}, {%4,%5,%6,%7}, {%8,%9}, {%0,%1,%2,%3};"
        : "+f"(c[0]), "+f"(c[1]), "+f"(c[2]), "+f"(c[3])
        : "r"(a[0]), "r"(a[1]), "r"(a[2]), "r"(a[3]), "r"(b0), "r"(b1));
}

// bf16 2-term split: p1 = bf16x2(a0,a1) (lo=a0), p2 = bf16x2 of residuals
__device__ __forceinline__ void bsplit(float a0, float a1, unsigned& p1, unsigned& p2) {
    asm("cvt.rn.bf16x2.f32 %0, %2, %1;" : "=r"(p1) : "f"(a0), "f"(a1));
    float b0 = __uint_as_float(p1 << 16);
    float b1 = __uint_as_float(p1 & 0xffff0000u);
    float r0 = a0 - b0, r1 = a1 - b1;
    asm("cvt.rn.bf16x2.f32 %0, %2, %1;" : "=r"(p2) : "f"(r0), "f"(r1));
}

// ---------------- fused: h = x@W (+splits, s/exp) AND adj packing ----------------
__global__ void __launch_bounds__(256) k_pre(const float* __restrict__ x,
                                             const float* __restrict__ W,
                                             const float* __restrict__ a_vec,
                                             const int* __restrict__ adj) {
    __shared__ float xs[64*128];
    int tid = threadIdx.x;

    if (blockIdx.x >= 256) {
        // ---- pack: one row, int4 loads, byte-assembled ballot ----
        int row = blockIdx.x - 256;
        int lane = tid & 31;
        const int4* src = (const int4*)(adj + (size_t)row*NN);
        int4 p = src[tid*2], q = src[tid*2+1];
        unsigned bb = ((p.x>0)?1u:0u) | ((p.y>0)?2u:0u) | ((p.z>0)?4u:0u) | ((p.w>0)?8u:0u)
                    | ((q.x>0)?16u:0u) | ((q.y>0)?32u:0u) | ((q.z>0)?64u:0u) | ((q.w>0)?128u:0u);
        unsigned v = bb << (8*(lane & 3));
        v |= __shfl_xor_sync(0xffffffffu, v, 1);
        v |= __shfl_xor_sync(0xffffffffu, v, 2);
        if ((lane & 3) == 0) g_adj[row*64 + (tid >> 2)] = v;
        return;
    }

    // ---- h-work: 64 rows per block, two 128-thread halves of 32 rows ----
    int hid = tid >> 7, t = tid & 127;
    int row0 = blockIdx.x * 64;
    for (int i = tid; i < 64*128; i += 256) xs[i] = x[(size_t)row0*128 + i];
    __syncthreads();

    float acc[32];
#pragma unroll
    for (int r = 0; r < 32; r++) acc[r] = 0.f;
    const float* xsl = xs + hid*32*128;
#pragma unroll 2
    for (int k = 0; k < 128; k++) {
        float wv = W[k*128 + t];
#pragma unroll
        for (int r = 0; r < 32; r++) acc[r] += xsl[r*128 + k] * wv;
    }
    int grow0 = row0 + hid*32;
    int b = grow0 >> 11, mbase = grow0 & 2047;
    {
        unsigned u1[16], u2[16];
#pragma unroll
        for (int k = 0; k < 16; k++) bsplit(acc[2*k], acc[2*k+1], u1[k], u2[k]);
        size_t base = ((size_t)(b*DD + t) * NN + mbase) >> 1;
        uint4* d1 = (uint4*)((unsigned*)g_hT1 + base);
        uint4* d2 = (uint4*)((unsigned*)g_hT2 + base);
#pragma unroll
        for (int k = 0; k < 4; k++) {
            d1[k] = *(uint4*)(u1 + 4*k);
            d2[k] = *(uint4*)(u2 + 4*k);
        }
    }
    __syncthreads();
#pragma unroll
    for (int r = 0; r < 32; r++) xs[(hid*32 + r)*128 + t] = acc[r];
    __syncthreads();
    int wid = tid >> 5, lane = tid & 31;
    float4 a14 = *(const float4*)(a_vec + lane*4);
    float4 a24 = *(const float4*)(a_vec + 128 + lane*4);
#pragma unroll
    for (int k = 0; k < 8; k++) {
        int r = wid*8 + k;
        float4 hv = *(const float4*)(xs + r*128 + lane*4);
        float s1 = hv.x*a14.x + hv.y*a14.y + hv.z*a14.z + hv.w*a14.w;
        float s2 = hv.x*a24.x + hv.y*a24.y + hv.z*a24.z + hv.w*a24.w;
#pragma unroll
        for (int o = 16; o; o >>= 1) {
            s1 += __shfl_xor_sync(0xffffffffu, s1, o);
            s2 += __shfl_xor_sync(0xffffffffu, s2, o);
        }
        if (lane == 0) {
            int gr = row0 + r;
            g_eA[gr] = __expf(s1);
            g_eC[gr] = __expf(NEG * s1);
            g_e12[gr] = make_float2(__expf(s2), __expf(NEG * s2));
        }
    }
}

// ---------------- smem layout (~83 KB → 2 CTAs/SM, L1D keeps ~62 KB) ----------------
#define SM_A1   0u          // 8 KB (64 x 128B)
#define SM_A2   8192u       // 8 KB
#define SM_B1   16384u      // 16 KB (128 x 128B)
#define SM_B2   32768u      // 16 KB
#define SM_E12  49152u      // 16 KB
#define SM_ADJ  65536u      // 16 KB (64 rows x 64 words)
#define SM_ROW  81920u      // 3 x 64 floats
#define SM_TOTAL (81920 + 768)

// ---------------- fused softmax + alpha + HMMA alpha@h ----------------
// grid (32, 8), block 256 (8 warps), 2 CTAs/SM
__global__ void __launch_bounds__(256, 2) k_main(float* __restrict__ out,
                                                 float* __restrict__ alpha) {
    extern __shared__ __align__(1024) char smem[];
    uint32_t sb = smem_to_u32(smem);
    int tid = threadIdx.x, wid = tid >> 5, lane = tid & 31;
    int b = blockIdx.y, n0 = blockIdx.x * TILE_N;

    float*    e12f = (float*)(smem + SM_E12);
    unsigned* adjs = (unsigned*)(smem + SM_ADJ);
    float* AiSh = (float*)(smem + SM_ROW);
    float* CiSh = AiSh + TILE_N;
    float* RvSh = CiSh + TILE_N;

    // stage e12 (16KB) and adj bitmask (16KB)
    {
        const uint4* s = (const uint4*)(g_e12 + b*NN);
        uint4* d = (uint4*)e12f;
#pragma unroll
        for (int k = 0; k < 4; k++) d[tid + k*256] = s[tid + k*256];
    }
    {
        const uint4* s = (const uint4*)(g_adj + (size_t)n0*64);
        uint4* d = (uint4*)adjs;
#pragma unroll
        for (int k = 0; k < 4; k++) d[tid + k*256] = s[tid + k*256];
    }
    if (tid < TILE_N) {
        AiSh[tid] = g_eA[b*NN + n0 + tid];
        CiSh[tid] = g_eC[b*NN + n0 + tid];
    }
    __syncthreads();

    // ---- pass B: row softmax denominators (8 rows per warp) ----
#pragma unroll 1
    for (int k = 0; k < 8; k++) {
        int r = wid*8 + k;
        float Ai = AiSh[r], Ci = CiSh[r];
        const unsigned* arow = adjs + r*64;
        float sum = 0.f;
#pragma unroll 4
        for (int i2 = 0; i2 < 32; i2++) {
            float4 ev = *(const float4*)(e12f + i2*128 + lane*4);
            unsigned bits = arow[i2*2 + (lane >> 4)];
            unsigned bp = (lane & 15) * 2;
            float nu0 = fmaxf(Ai*ev.x, Ci*ev.y);
            float nu1 = fmaxf(Ai*ev.z, Ci*ev.w);
            sum += ((bits >> bp) & 1u) ? nu0 : 0.f;
            sum += ((bits >> (bp+1)) & 1u) ? nu1 : 0.f;
        }
#pragma unroll
        for (int o = 16; o; o >>= 1) sum += __shfl_xor_sync(0xffffffffu, sum, o);
        if (lane == 0) RvSh[r] = 1.f / sum;
    }
    __syncthreads();

    // alpha mapping: row = tid>>2, 16-m quarter = tid&3
    int arw = tid >> 2, mq = tid & 3;
    float Ai = AiSh[arw], Ci = CiSh[arw], Rv = RvSh[arw];
    float* aout = alpha + ((size_t)(b*NN + n0 + arw)) * NN;

    // B staging via reg prefetch: 4 rows/thread/split (rows brow+32i)
    int brow = tid >> 3, bq = tid & 7;
    size_t gbase = ((size_t)(b*128 + brow))*256 + bq;     // uint4 units
    unsigned bsw = SW128((unsigned)(brow*128 + bq*16));
    const uint4* gB1 = (const uint4*)g_hT1;
    const uint4* gB2 = (const uint4*)g_hT2;

    // warp GEMM tiling: warp -> n-half 32, d-quarter 32
    int n0w = (wid >> 2) * 32, d0w = (wid & 3) * 32;
    int arow_l = lane & 15;
    unsigned acol_l = (lane >> 4) * 16;
    int brow_l = (lane & 7) + ((lane >> 4) << 3);
    unsigned bcol_l = ((lane >> 3) & 1) * 16;
    unsigned a_xor = (unsigned)((arow_l & 7) << 4);
    unsigned b_xor = (unsigned)((brow_l & 7) << 4);
    uint32_t a_row_base = sb + SM_A1 + (unsigned)((n0w + arow_l) * 128);
    uint32_t b_row_base = sb + SM_B1 + (unsigned)((d0w + brow_l) * 128);

    float acc[2][4][4];
#pragma unroll
    for (int i = 0; i < 2; i++)
#pragma unroll
        for (int j = 0; j < 4; j++)
#pragma unroll
            for (int k = 0; k < 4; k++) acc[i][j][k] = 0.f;

    // prefetch chunk 0
    uint4 v1[4], v2[4];
#pragma unroll
    for (int i = 0; i < 4; i++) {
        v1[i] = gB1[gbase + (size_t)i*8192];
        v2[i] = gB2[gbase + (size_t)i*8192];
    }

    for (int c = 0; c < NCHUNKS; c++) {
        int m0 = c * KCHUNK;
        // STS B tiles
#pragma unroll
        for (int i = 0; i < 4; i++) {
            *(uint4*)(smem + SM_B1 + bsw + i*4096) = v1[i];
            *(uint4*)(smem + SM_B2 + bsw + i*4096) = v2[i];
        }
        // alpha: 16 m per thread (streaming fp32 STG + bf16 split STS)
        unsigned bits = adjs[arw*64 + c*2 + (mq >> 1)];
        unsigned shbase = (mq & 1) * 16;
#pragma unroll
        for (int g = 0; g < 4; g++) {
            int mloc = mq*16 + g*4;
            int m = m0 + mloc;
            float4 e01 = *(const float4*)(e12f + 2*m);
            float4 e23 = *(const float4*)(e12f + 2*m + 4);
            float n0v = fmaxf(Ai*e01.x, Ci*e01.y);
            float n1v = fmaxf(Ai*e01.z, Ci*e01.w);
            float n2v = fmaxf(Ai*e23.x, Ci*e23.y);
            float n3v = fmaxf(Ai*e23.z, Ci*e23.w);
            unsigned bp = shbase + g*4;
            float a0 = ((bits >> (bp+0)) & 1u) ? n0v*Rv : 0.f;
            float a1 = ((bits >> (bp+1)) & 1u) ? n1v*Rv : 0.f;
            float a2 = ((bits >> (bp+2)) & 1u) ? n2v*Rv : 0.f;
            float a3 = ((bits >> (bp+3)) & 1u) ? n3v*Rv : 0.f;
            __stwt((float4*)(aout + m), make_float4(a0, a1, a2, a3));
            unsigned p1a, p2a, p1b, p2b;
            bsplit(a0, a1, p1a, p2a);
            bsplit(a2, a3, p1b, p2b);
            unsigned so = SW128((unsigned)(arw*128 + mloc*2));
            *(uint2*)(smem + SM_A1 + so) = make_uint2(p1a, p1b);
            *(uint2*)(smem + SM_A2 + so) = make_uint2(p2a, p2b);
        }
        __syncthreads();

        // prefetch next chunk (hidden under the MMA phase)
        if (c + 1 < NCHUNKS) {
            size_t mo = (size_t)((m0 + KCHUNK) >> 3);
#pragma unroll
            for (int i = 0; i < 4; i++) {
                v1[i] = gB1[gbase + (size_t)i*8192 + mo];
                v2[i] = gB2[gbase + (size_t)i*8192 + mo];
            }
        }

        // MMA: 4 k-steps of 16, term-major ordering
#pragma unroll
        for (int ks = 0; ks < 4; ks++) {
            unsigned acol = (acol_l + ks*32) ^ a_xor;
            unsigned bcol = (bcol_l + ks*32) ^ b_xor;
            uint32_t a1f[2][4], a2f[2][4], b1f[2][4], b2f[2][4];
#pragma unroll
            for (int ng = 0; ng < 2; ng++) {
                ldsm4(a1f[ng], a_row_base + ng*2048 + acol);
                ldsm4(a2f[ng], a_row_base + ng*2048 + acol + 8192u);
            }
#pragma unroll
            for (int dg = 0; dg < 2; dg++) {
                ldsm4(b1f[dg], b_row_base + dg*2048 + bcol);
                ldsm4(b2f[dg], b_row_base + dg*2048 + bcol + 16384u);
            }
#pragma unroll
            for (int ng = 0; ng < 2; ng++)
#pragma unroll
                for (int dg = 0; dg < 2; dg++) {
                    mma_bf16(acc[ng][dg*2+0], a1f[ng], b1f[dg][0], b1f[dg][1]);
                    mma_bf16(acc[ng][dg*2+1], a1f[ng], b1f[dg][2], b1f[dg][3]);
                }
#pragma unroll
            for (int ng = 0; ng < 2; ng++)
#pragma unroll
                for (int dg = 0; dg < 2; dg++) {
                    mma_bf16(acc[ng][dg*2+0], a1f[ng], b2f[dg][0], b2f[dg][1]);
                    mma_bf16(acc[ng][dg*2+1], a1f[ng], b2f[dg][2], b2f[dg][3]);
                }
#pragma unroll
            for (int ng = 0; ng < 2; ng++)
#pragma unroll
                for (int dg = 0; dg < 2; dg++) {
                    mma_bf16(acc[ng][dg*2+0], a2f[ng], b1f[dg][0], b1f[dg][1]);
                    mma_bf16(acc[ng][dg*2+1], a2f[ng], b1f[dg][2], b1f[dg][3]);
                }
        }
        __syncthreads();
    }

    // epilogue: write out tile
#pragma unroll
    for (int ng = 0; ng < 2; ng++) {
#pragma unroll
        for (int dt = 0; dt < 4; dt++) {
            int r = n0 + n0w + ng*16 + (lane >> 2);
            int col = d0w + dt*8 + (lane & 3)*2;
            float* p = out + ((size_t)(b*NN + r))*DD + col;
            *(float2*)p = make_float2(acc[ng][dt][0], acc[ng][dt][1]);
            *(float2*)(p + 8*DD) = make_float2(acc[ng][dt][2], acc[ng][dt][3]);
        }
    }
}

// ---------------- launch ----------------
extern "C" void kernel_launch(void* const* d_in, const int* in_sizes, int n_in,
                              void* d_out, int out_size) {
    const float* x    = (const float*)d_in[0];
    const int*   adj  = (const int*)  d_in[1];
    const float* W    = (const float*)d_in[2];
    const float* avec = (const float*)d_in[3];
    float* out   = (float*)d_out;
    float* alpha = out + (size_t)BN*DD;

    cudaFuncSetAttribute(k_main, cudaFuncAttributeMaxDynamicSharedMemorySize,
                         SM_TOTAL);

    k_pre<<<256 + NN, 256>>>(x, W, avec, adj);
    dim3 grid(NN/TILE_N, BB);
    k_main<<<grid, 256, SM_TOTAL>>>(out, alpha);
}